// round 16
// baseline (speedup 1.0000x reference)
#include <cuda_runtime.h>
#include <cuda_bf16.h>

// USER_NUM=1000, SKILL_NUM=256, K_HIDDEN=128, N_ITEMS=4096, SEQ_LEN=8192
// out[l, k] = sum_{s : Q[items[l], s] != 0} E[user, s, k]
//
// ONE kernel, no global scratch, no device barrier:
//   CTA = 8 warps = 2 positions. Each warp computes one QUARTER (64 skills)
//   of one position: ~6.4 gathers, all in one predicated batch (1 latency
//   round). Partials combined across the 4 warps of a position via smem +
//   one __syncthreads, then stored coalesced.

#define SEQ_LEN   8192
#define N_ITEMS   4096
#define SKILLS    256
#define K_HIDDEN  128
#define NNZ_CAP   32          // binomial(64,0.1): mean 6.4, std 2.4
#define CTA_THREADS 256
#define POS_PER_CTA 2         // 8 warps / 4 quarters

__global__ void __launch_bounds__(CTA_THREADS)
item_emb_quarter_smem(const int* __restrict__ user_p,
                      const float* __restrict__ Q,     // [N_ITEMS, SKILLS]
                      const int* __restrict__ items,   // [SEQ_LEN]
                      const float* __restrict__ emb,   // [USER_NUM, SKILLS, K_HIDDEN]
                      float4* __restrict__ out4)       // [SEQ_LEN * 32]
{
    __shared__ int    sidx[8][NNZ_CAP];
    __shared__ float4 s_part[8][32];      // per-warp partial rows (4 KB)

    const int tid  = threadIdx.x;
    const int w    = tid >> 5;            // 0..7
    const int lane = tid & 31;
    const int p    = w >> 2;              // position slot in CTA: 0..1
    const int quar = w & 3;               // skill quarter: 0..3
    const int pos  = blockIdx.x * POS_PER_CTA + p;   // grid sized exactly

    const int user = user_p[0];
    const float4* __restrict__ E4 =
        reinterpret_cast<const float4*>(emb + (long long)user * SKILLS * K_HIDDEN) + lane;

    const int item = __ldg(&items[pos]);  // broadcast (4 warps share it)

    // This quarter's 64 skills: one coalesced float2 per lane (LDG.64)
    const float2 v = reinterpret_cast<const float2*>(
        Q + (long long)item * SKILLS + quar * 64)[lane];

    // Ballot-compact nonzero skill ids (2 ballots)
    const int s_base = quar * 64 + 2 * lane;
    const float vals[2] = {v.x, v.y};
    const unsigned lt_mask = (1u << lane) - 1u;
    int nnz = 0;
    #pragma unroll
    for (int t = 0; t < 2; t++) {
        const bool nz = (vals[t] != 0.0f);
        const unsigned m = __ballot_sync(0xffffffffu, nz);
        if (nz) {
            const int pdx = nnz + __popc(m & lt_mask);
            if (pdx < NNZ_CAP) sidx[w][pdx] = s_base + t;
        }
        nnz += __popc(m);
    }
    __syncwarp();
    nnz = min(nnz, NNZ_CAP);

    // Gather-accumulate: predicated batch of 8 -> typical nnz 6.4 = ONE round
    float4 acc = make_float4(0.f, 0.f, 0.f, 0.f);
    for (int j0 = 0; j0 < nnz; j0 += 8) {
        float4 e[8];
        #pragma unroll
        for (int t = 0; t < 8; t++) {
            const int j = j0 + t;
            e[t] = (j < nnz) ? E4[sidx[w][j] * 32]
                             : make_float4(0.f, 0.f, 0.f, 0.f);
        }
        acc.x += ((e[0].x + e[1].x) + (e[2].x + e[3].x))
               + ((e[4].x + e[5].x) + (e[6].x + e[7].x));
        acc.y += ((e[0].y + e[1].y) + (e[2].y + e[3].y))
               + ((e[4].y + e[5].y) + (e[6].y + e[7].y));
        acc.z += ((e[0].z + e[1].z) + (e[2].z + e[3].z))
               + ((e[4].z + e[5].z) + (e[6].z + e[7].z));
        acc.w += ((e[0].w + e[1].w) + (e[2].w + e[3].w))
               + ((e[4].w + e[5].w) + (e[6].w + e[7].w));
    }

    s_part[w][lane] = acc;
    __syncthreads();

    // Combine the 4 quarter-partials of each position; warps 0 and 4 store.
    if (quar == 0) {
        const float4 r0 = s_part[p * 4 + 0][lane];
        const float4 r1 = s_part[p * 4 + 1][lane];
        const float4 r2 = s_part[p * 4 + 2][lane];
        const float4 r3 = s_part[p * 4 + 3][lane];
        float4 o;
        o.x = (r0.x + r1.x) + (r2.x + r3.x);
        o.y = (r0.y + r1.y) + (r2.y + r3.y);
        o.z = (r0.z + r1.z) + (r2.z + r3.z);
        o.w = (r0.w + r1.w) + (r2.w + r3.w);
        out4[pos * 32 + lane] = o;        // coalesced 512B store per warp
    }
}

extern "C" void kernel_launch(void* const* d_in, const int* in_sizes, int n_in,
                              void* d_out, int out_size)
{
    const int*   user  = nullptr;
    const float* Q     = nullptr;
    const int*   items = nullptr;
    const float* emb   = nullptr;

    for (int i = 0; i < n_in; i++) {
        switch (in_sizes[i]) {
            case 1:                        user  = (const int*)  d_in[i]; break;
            case N_ITEMS * SKILLS:         Q     = (const float*)d_in[i]; break;
            case SEQ_LEN:                  items = (const int*)  d_in[i]; break;
            case 1000 * SKILLS * K_HIDDEN: emb   = (const float*)d_in[i]; break;
            default: break;
        }
    }
    if (!user)  user  = (const int*)  d_in[0];
    if (!Q)     Q     = (const float*)d_in[1];
    if (!items) items = (const int*)  d_in[2];
    if (!emb)   emb   = (const float*)d_in[3];

    // ONE launch: 4096 CTAs x 256 threads, 2 positions per CTA
    item_emb_quarter_smem<<<SEQ_LEN / POS_PER_CTA, CTA_THREADS>>>(
        user, Q, items, emb, (float4*)d_out);
}

// round 17
// speedup vs baseline: 1.1376x; 1.1376x over previous
#include <cuda_runtime.h>
#include <cuda_bf16.h>

// USER_NUM=1000, SKILL_NUM=256, K_HIDDEN=128, N_ITEMS=4096, SEQ_LEN=8192
// out[l, k] = sum_{s : Q[items[l], s] != 0} E[user, s, k]
//
// ONE lean kernel (R16 lesson: this family is ISSUED-INSTRUCTION bound;
// R16 burned 5.9M instrs on predication + quarter-split prologues):
//   warp = (position, half-of-256-skills): 1 Q load + 4 ballots + ~13
//   unpredicated gathers; warp pair combines via smem; even warp stores.
//   ~2.6M total instructions, no scratch, no barrier, no second kernel.

#define SEQ_LEN   8192
#define N_ITEMS   4096
#define SKILLS    256
#define K_HIDDEN  128
#define NNZ_CAP   64          // binomial(128,0.1): mean 12.8, std 3.4
#define CTA_THREADS 256
#define CTA_WARPS   8
#define POS_PER_CTA (CTA_WARPS / 2)   // 4

__global__ void __launch_bounds__(CTA_THREADS)
item_emb_halfsplit(const int* __restrict__ user_p,
                   const float* __restrict__ Q,     // [N_ITEMS, SKILLS]
                   const int* __restrict__ items,   // [SEQ_LEN]
                   const float* __restrict__ emb,   // [USER_NUM, SKILLS, K_HIDDEN]
                   float4* __restrict__ out4)       // [SEQ_LEN * 32]
{
    __shared__ int    sidx[CTA_WARPS][NNZ_CAP];
    __shared__ float4 s_part[CTA_WARPS][32];        // 4 KB

    const int tid  = threadIdx.x;
    const int w    = tid >> 5;            // 0..7
    const int lane = tid & 31;
    const int pslot = w >> 1;             // 0..3 position slot
    const int half  = w & 1;              // 0..1 skill half
    const int pos   = blockIdx.x * POS_PER_CTA + pslot;  // exact grid

    const int user = user_p[0];
    const float4* __restrict__ E4 =
        reinterpret_cast<const float4*>(emb + (long long)user * SKILLS * K_HIDDEN) + lane;

    const int item = __ldg(&items[pos]);  // broadcast; warp pair shares value

    // This half's 128 skills: one coalesced float4 per lane
    const float4 v = reinterpret_cast<const float4*>(
        Q + (long long)item * SKILLS + half * 128)[lane];

    // Ballot-compact nonzero skill ids (4 ballots)
    const int s_base = half * 128 + 4 * lane;
    const float vals[4] = {v.x, v.y, v.z, v.w};
    const unsigned lt_mask = (1u << lane) - 1u;
    int nnz = 0;
    #pragma unroll
    for (int t = 0; t < 4; t++) {
        const bool nz = (vals[t] != 0.0f);
        const unsigned m = __ballot_sync(0xffffffffu, nz);
        if (nz) {
            const int p = nnz + __popc(m & lt_mask);
            if (p < NNZ_CAP) sidx[w][p] = s_base + t;
        }
        nnz += __popc(m);
    }
    __syncwarp();
    nnz = min(nnz, NNZ_CAP);

    // Gather-accumulate (proven R11 inner loop): 8-batch, 4-batch, tail
    float4 a0 = make_float4(0.f, 0.f, 0.f, 0.f);
    float4 a1 = make_float4(0.f, 0.f, 0.f, 0.f);
    int j = 0;
    for (; j + 8 <= nnz; j += 8) {
        int s[8];
        #pragma unroll
        for (int t = 0; t < 8; t++) s[t] = sidx[w][j + t];
        float4 e[8];
        #pragma unroll
        for (int t = 0; t < 8; t++) e[t] = E4[s[t] * 32];
        #pragma unroll
        for (int t = 0; t < 4; t++) {
            a0.x += e[t].x;   a0.y += e[t].y;   a0.z += e[t].z;   a0.w += e[t].w;
            a1.x += e[t+4].x; a1.y += e[t+4].y; a1.z += e[t+4].z; a1.w += e[t+4].w;
        }
    }
    if (j + 4 <= nnz) {
        const int s0 = sidx[w][j+0], s1 = sidx[w][j+1];
        const int s2 = sidx[w][j+2], s3 = sidx[w][j+3];
        const float4 e0 = E4[s0 * 32];
        const float4 e1 = E4[s1 * 32];
        const float4 e2 = E4[s2 * 32];
        const float4 e3 = E4[s3 * 32];
        a0.x += (e0.x + e1.x) + (e2.x + e3.x);
        a0.y += (e0.y + e1.y) + (e2.y + e3.y);
        a0.z += (e0.z + e1.z) + (e2.z + e3.z);
        a0.w += (e0.w + e1.w) + (e2.w + e3.w);
        j += 4;
    }
    for (; j < nnz; j++) {
        const float4 e = E4[sidx[w][j] * 32];
        a1.x += e.x; a1.y += e.y; a1.z += e.z; a1.w += e.w;
    }

    float4 acc;
    acc.x = a0.x + a1.x; acc.y = a0.y + a1.y;
    acc.z = a0.z + a1.z; acc.w = a0.w + a1.w;

    s_part[w][lane] = acc;
    __syncthreads();

    // Even warp of each pair combines the two halves; one coalesced store.
    if (half == 0) {
        const float4 r0 = s_part[w][lane];
        const float4 r1 = s_part[w + 1][lane];
        float4 o;
        o.x = r0.x + r1.x; o.y = r0.y + r1.y;
        o.z = r0.z + r1.z; o.w = r0.w + r1.w;
        out4[pos * 32 + lane] = o;
    }
}

extern "C" void kernel_launch(void* const* d_in, const int* in_sizes, int n_in,
                              void* d_out, int out_size)
{
    const int*   user  = nullptr;
    const float* Q     = nullptr;
    const int*   items = nullptr;
    const float* emb   = nullptr;

    for (int i = 0; i < n_in; i++) {
        switch (in_sizes[i]) {
            case 1:                        user  = (const int*)  d_in[i]; break;
            case N_ITEMS * SKILLS:         Q     = (const float*)d_in[i]; break;
            case SEQ_LEN:                  items = (const int*)  d_in[i]; break;
            case 1000 * SKILLS * K_HIDDEN: emb   = (const float*)d_in[i]; break;
            default: break;
        }
    }
    if (!user)  user  = (const int*)  d_in[0];
    if (!Q)     Q     = (const float*)d_in[1];
    if (!items) items = (const int*)  d_in[2];
    if (!emb)   emb   = (const float*)d_in[3];

    // ONE launch: 2048 CTAs x 256 threads, 4 positions per CTA
    item_emb_halfsplit<<<SEQ_LEN / POS_PER_CTA, CTA_THREADS>>>(
        user, Q, items, emb, (float4*)d_out);
}